// round 7
// baseline (speedup 1.0000x reference)
#include <cuda_runtime.h>

#define NODES_MAX 50000
#define F 128

// Scratch (no runtime allocation allowed)
__device__ float g_P[NODES_MAX * F];       // h @ W1h^T + b1
__device__ float g_sums[NODES_MAX * F];    // segment sums of leaky acts
__device__ float g_counts[NODES_MAX];      // in-degree
__device__ float g_W1T[F * F];             // [k][c] = W1[c*131 + k]
__device__ float g_W2T[256 * F];           // [k][c] = W2[c*256 + k]

// ---------------------------------------------------------------------------
// Prep: transpose weights, zero accumulators
// ---------------------------------------------------------------------------
__global__ void prep_kernel(const float* __restrict__ W1,
                            const float* __restrict__ W2,
                            int n_nodes)
{
    int idx = blockIdx.x * blockDim.x + threadIdx.x;
    int stride = gridDim.x * blockDim.x;

    for (int i = idx; i < F * F; i += stride) {
        int c = i >> 7, k = i & 127;
        g_W1T[k * F + c] = W1[c * 131 + k];
    }
    for (int i = idx; i < 256 * F; i += stride) {
        int c = i & 127, k = i >> 7;
        g_W2T[k * F + c] = W2[c * 256 + k];
    }
    int nsum4 = (n_nodes * F) >> 2;
    float4* s4 = reinterpret_cast<float4*>(g_sums);
    float4 z = make_float4(0.f, 0.f, 0.f, 0.f);
    for (int i = idx; i < nsum4; i += stride) s4[i] = z;
    for (int i = idx; i < n_nodes; i += stride) g_counts[i] = 0.f;
}

// ---------------------------------------------------------------------------
// Core GEMM tile: 128x64 block, 8x4 micro-tile, FFMA2 inner loop,
// double-buffered smem, BK=8, 256 threads, 3 CTAs/SM target.
// C[row0:+128][col0:+64] = A(Mx128) x Bt(KTOTx128, [k][c]).
// KTOT = 256: k<128 from A1, k>=128 from A2 scaled by 1/max(count,1).
// ---------------------------------------------------------------------------
template<int KTOT, bool RELU>
__device__ __forceinline__ void gemm_tile(
    const float* __restrict__ A1, const float* __restrict__ A2,
    const float* __restrict__ Bt, const float* __restrict__ bias,
    float* __restrict__ out, int M, int row0, int col0)
{
    __shared__ float As[2][8][132];   // [k][m], padded
    __shared__ float Bs[2][8][64];    // [k][c]

    const int tid = threadIdx.x;
    const int tx = tid & 15;          // 16 col groups x 4 cols
    const int ty = tid >> 4;          // 16 row groups (split 4+4 rows)

    // A loader: one float4 per thread per tile (128 rows x 8 k)
    const int lm = tid >> 1;
    const int lk = (tid & 1) * 4;
    const int grow = row0 + lm;
    const bool arow_ok = (grow < M);

    // B loader: one float2 per thread per tile (8 k x 64 cols)
    const int bk = tid >> 5;          // 0..7
    const int bc = (tid & 31) * 2;    // 0..62

    float inv = 1.0f;
    if (KTOT == 256)
        inv = arow_ok ? (1.0f / fmaxf(g_counts[grow], 1.0f)) : 0.0f;

    unsigned long long acc[8][2];
    #pragma unroll
    for (int i = 0; i < 8; i++) {
        acc[i][0] = 0ull; acc[i][1] = 0ull;
    }

    auto loadA = [&](int k0) -> float4 {
        float4 v = make_float4(0.f, 0.f, 0.f, 0.f);
        if (arow_ok) {
            if (KTOT == 256 && k0 >= 128) {
                v = *(const float4*)(A2 + (long)grow * 128 + (k0 - 128) + lk);
                v.x *= inv; v.y *= inv; v.z *= inv; v.w *= inv;
            } else {
                v = *(const float4*)(A1 + (long)grow * 128 + k0 + lk);
            }
        }
        return v;
    };
    auto loadB = [&](int k0) -> float2 {
        return *(const float2*)(Bt + (k0 + bk) * 128 + col0 + bc);
    };
    auto storeS = [&](int b, float4 ra, float2 rb) {
        As[b][lk + 0][lm] = ra.x;
        As[b][lk + 1][lm] = ra.y;
        As[b][lk + 2][lm] = ra.z;
        As[b][lk + 3][lm] = ra.w;
        *(float2*)&Bs[b][bk][bc] = rb;
    };
    auto compute = [&](const float (*As_)[132], const float (*Bs_)[64]) {
        #pragma unroll
        for (int k = 0; k < 8; k++) {
            float a[8];
            *(float4*)&a[0] = *(const float4*)&As_[k][ty * 4];
            *(float4*)&a[4] = *(const float4*)&As_[k][64 + ty * 4];
            unsigned long long bp[2];
            double2 d0 = *(const double2*)&Bs_[k][tx * 4];
            bp[0] = __double_as_longlong(d0.x);
            bp[1] = __double_as_longlong(d0.y);
            #pragma unroll
            for (int i = 0; i < 8; i++) {
                unsigned long long ad;
                asm("mov.b64 %0, {%1, %2};" : "=l"(ad) : "f"(a[i]), "f"(a[i]));
                asm("fma.rn.f32x2 %0, %1, %2, %0;"
                    : "+l"(acc[i][0]) : "l"(ad), "l"(bp[0]));
                asm("fma.rn.f32x2 %0, %1, %2, %0;"
                    : "+l"(acc[i][1]) : "l"(ad), "l"(bp[1]));
            }
        }
    };

    // prologue: fill buffer 0
    storeS(0, loadA(0), loadB(0));
    __syncthreads();

    #pragma unroll 1
    for (int k0 = 0; k0 < KTOT; k0 += 16) {
        {
            float4 ra; float2 rb;
            bool nxt = (k0 + 8) < KTOT;
            if (nxt) { ra = loadA(k0 + 8); rb = loadB(k0 + 8); }
            compute(As[0], Bs[0]);
            if (nxt) {
                storeS(1, ra, rb);
                __syncthreads();
            }
        }
        if ((k0 + 8) < KTOT) {
            float4 ra; float2 rb;
            bool nxt = (k0 + 16) < KTOT;
            if (nxt) { ra = loadA(k0 + 16); rb = loadB(k0 + 16); }
            compute(As[1], Bs[1]);
            if (nxt) {
                storeS(0, ra, rb);
                __syncthreads();
            }
        }
    }

    const int c0 = col0 + tx * 4;
    float4 bias0 = *(const float4*)(bias + c0);

    #pragma unroll
    for (int i = 0; i < 8; i++) {
        int gr = row0 + ((i < 4) ? (ty * 4 + i) : (64 + ty * 4 + i - 4));
        if (gr >= M) continue;
        float4 v0;
        asm("mov.b64 {%0, %1}, %2;" : "=f"(v0.x), "=f"(v0.y) : "l"(acc[i][0]));
        asm("mov.b64 {%0, %1}, %2;" : "=f"(v0.z), "=f"(v0.w) : "l"(acc[i][1]));
        v0.x += bias0.x; v0.y += bias0.y; v0.z += bias0.z; v0.w += bias0.w;
        if (RELU) {
            v0.x = fmaxf(v0.x, 0.f); v0.y = fmaxf(v0.y, 0.f);
            v0.z = fmaxf(v0.z, 0.f); v0.w = fmaxf(v0.w, 0.f);
        }
        *(float4*)(out + (long)gr * 128 + c0) = v0;
    }
}

// ---------------------------------------------------------------------------
// GEMM1: g_P = h @ W1h^T + b1
// ---------------------------------------------------------------------------
__global__ __launch_bounds__(256, 3) void gemm1_kernel(
    const float* __restrict__ h, const float* __restrict__ b1, int M)
{
    gemm_tile<128, false>(h, nullptr, g_W1T, b1, g_P, M,
                          (blockIdx.x >> 1) * 128, (blockIdx.x & 1) * 64);
}

// ---------------------------------------------------------------------------
// Edge kernel (proven): one warp per edge, x4 unrolled grid-stride,
// red.global.add.v4.f32 scatter into g_sums, count bump by lane 0.
// ---------------------------------------------------------------------------
__global__ __launch_bounds__(256) void edge_kernel(
    const int* __restrict__ src, const int* __restrict__ dst,
    const float* __restrict__ ew, const float* __restrict__ W1, int E)
{
    __shared__ float cw[3][128];
    for (int i = threadIdx.x; i < 384; i += 256) {
        int t = i >> 7, j = i & 127;
        cw[t][j] = W1[j * 131 + 128 + t];
    }
    __syncthreads();

    const int lane = threadIdx.x & 31;
    const int col  = lane * 4;
    const float4 cA = *(const float4*)&cw[0][col];
    const float4 cB = *(const float4*)&cw[1][col];
    const float4 cC = *(const float4*)&cw[2][col];

    const int gwarp  = (blockIdx.x * 256 + threadIdx.x) >> 5;
    const int nwarps = (gridDim.x * 256) >> 5;

    for (int e0 = gwarp; e0 < E; e0 += nwarps * 4) {
        int   se[4], de[4];
        float w0[4], w1[4], w2[4];
        float4 p[4];
        bool  v[4];

        #pragma unroll
        for (int u = 0; u < 4; u++) {
            int e = e0 + u * nwarps;
            v[u] = (e < E);
            if (v[u]) {
                se[u] = src[e];
                de[u] = dst[e];
                w0[u] = ew[e * 3 + 0];
                w1[u] = ew[e * 3 + 1];
                w2[u] = ew[e * 3 + 2];
            }
        }
        #pragma unroll
        for (int u = 0; u < 4; u++)
            if (v[u]) p[u] = *(const float4*)(g_P + (long)se[u] * 128 + col);

        #pragma unroll
        for (int u = 0; u < 4; u++) {
            if (!v[u]) continue;
            float t0 = p[u].x + w0[u] * cA.x + w1[u] * cB.x + w2[u] * cC.x;
            float t1 = p[u].y + w0[u] * cA.y + w1[u] * cB.y + w2[u] * cC.y;
            float t2 = p[u].z + w0[u] * cA.z + w1[u] * cB.z + w2[u] * cC.z;
            float t3 = p[u].w + w0[u] * cA.w + w1[u] * cB.w + w2[u] * cC.w;
            t0 = (t0 < 0.f) ? 0.01f * t0 : t0;
            t1 = (t1 < 0.f) ? 0.01f * t1 : t1;
            t2 = (t2 < 0.f) ? 0.01f * t2 : t2;
            t3 = (t3 < 0.f) ? 0.01f * t3 : t3;
            float* addr = g_sums + (long)de[u] * 128 + col;
            asm volatile("red.global.add.v4.f32 [%0], {%1, %2, %3, %4};"
                         :: "l"(addr), "f"(t0), "f"(t1), "f"(t2), "f"(t3)
                         : "memory");
            if (lane == 0) atomicAdd(&g_counts[de[u]], 1.0f);
        }
    }
}

// ---------------------------------------------------------------------------
// GEMM2 (K=256): out = relu( [h | g_sums*inv_count] @ W2^T + b2 )
// ---------------------------------------------------------------------------
__global__ __launch_bounds__(256, 3) void gemm2_kernel(
    const float* __restrict__ h, const float* __restrict__ b2,
    float* __restrict__ out, int M)
{
    gemm_tile<256, true>(h, g_sums, g_W2T, b2, out, M,
                         (blockIdx.x >> 1) * 128, (blockIdx.x & 1) * 64);
}

// ---------------------------------------------------------------------------
extern "C" void kernel_launch(void* const* d_in, const int* in_sizes, int n_in,
                              void* d_out, int out_size)
{
    const float* h    = (const float*)d_in[0];
    const int*   esrc = (const int*)  d_in[1];
    const int*   edst = (const int*)  d_in[2];
    const float* ew   = (const float*)d_in[3];
    const float* W1   = (const float*)d_in[4];
    const float* b1   = (const float*)d_in[5];
    const float* W2   = (const float*)d_in[6];
    const float* b2   = (const float*)d_in[7];
    float* out = (float*)d_out;

    int M = in_sizes[0] / 128;    // 50000 nodes
    int E = in_sizes[1];          // 800000 edges
    int nT = (M + 127) / 128;     // 391 row tiles
    int nB = nT * 2;              // x2 col tiles (64 wide)

    prep_kernel<<<512, 256>>>(W1, W2, M);
    gemm1_kernel<<<nB, 256>>>(h, b1, M);
    edge_kernel<<<1480, 256>>>(esrc, edst, ew, W1, E);
    gemm2_kernel<<<nB, 256>>>(h, b2, out, M);
}